// round 16
// baseline (speedup 1.0000x reference)
#include <cuda_runtime.h>
#include <math.h>

// Problem constants
#define BB   64
#define TT   512
#define EE   300
#define HDIM 256
#define G4   1024
#define KTAG 20
#define GRID_P 128

typedef unsigned long long ull;

// ---------------- scratch ----------------
// g_X blocked: [dir][bt][ks][t][b_l][gate][k_l]
__device__ float g_X[(size_t)2 * BB * TT * G4];
// g_h blocked: [dir][bt][t][b_l][k]
__device__ float g_h[(size_t)2 * BB * TT * HDIM];
__device__ float g_emis[(size_t)BB * TT * KTAG];
// per-(group, producerCTA, producerWarp[4]) monotone flags, 128B apart
__device__ int   g_flagsB[16 * 8 * 4 * 32];

// ---------------- packed fp32x2 helpers ----------------
__device__ __forceinline__ ull ffma2(ull a, ull b, ull c) {
    ull d;
    asm("fma.rn.f32x2 %0, %1, %2, %3;" : "=l"(d) : "l"(a), "l"(b), "l"(c));
    return d;
}
__device__ __forceinline__ float2 u2f2(ull v) {
    float2 f;
    asm("mov.b64 {%0, %1}, %2;" : "=f"(f.x), "=f"(f.y) : "l"(v));
    return f;
}
// ---------------- tf32 helpers ----------------
__device__ __forceinline__ unsigned tf32hi(float x) {
    unsigned r;
    asm("cvt.rna.tf32.f32 %0, %1;" : "=r"(r) : "f"(x));
    return r;
}
__device__ __forceinline__ uint2 tf32pair(float x) {
    unsigned h = tf32hi(x);
    float rem = x - __uint_as_float(h);
    unsigned l = tf32hi(rem);
    return make_uint2(h, l);
}
#define MMA_TF32(c, a, b) \
    asm volatile("mma.sync.aligned.m16n8k8.row.col.f32.tf32.tf32.f32 " \
        "{%0,%1,%2,%3}, {%4,%5,%6,%7}, {%8,%9}, {%0,%1,%2,%3};" \
        : "+f"((c)[0]), "+f"((c)[1]), "+f"((c)[2]), "+f"((c)[3]) \
        : "r"((a)[0]), "r"((a)[1]), "r"((a)[2]), "r"((a)[3]), \
          "r"((b)[0]), "r"((b)[1]))

#define BARL() asm volatile("bar.sync 4, 128;" ::: "memory")
#define BARG() asm volatile("bar.sync 5, 256;" ::: "memory")

__device__ __forceinline__ float sigf(float x) { return 1.f / (1.f + expf(-x)); }

// =====================================================================
// FUSED persistent kernel: 128 CTAs x 384 threads.
//   warps 0-7  : gates GEMM, tensor pipe (3xTF32), hi/lo PRE-STAGED
//   warps 8-11 : LSTM (1/SMSP, HIGH wid priority), cached xprog poll
// =====================================================================
#define WP_ULL (4 * 128 * 33)
// Wp 135168 | hsm 8192 | ps 32768 | As2 16896 | Bs2 16896 | tok 512 | xprog 128
#define SMEM_FUSED 210560

__global__ void __launch_bounds__(384, 1)
fused_persistent_kernel(const int* __restrict__ sentence,
                        const int* __restrict__ lengths,
                        const float* __restrict__ emb,
                        const float* __restrict__ Wf_ih,
                        const float* __restrict__ bf,
                        const float* __restrict__ Wb_ih,
                        const float* __restrict__ bb,
                        const float* __restrict__ Wf_hh,
                        const float* __restrict__ Wb_hh)
{
    extern __shared__ char smraw[];
    ull*   Wp   = (ull*)smraw;                   // [4][128][33]
    float* hsm  = (float*)(Wp + WP_ULL);         // 4 warps x [8b][64k]
    float* ps   = hsm + 2048;                    // [2][4][4][8][32] psum
    uint2* As2  = (uint2*)(ps + 8192);           // [16][132] (hi,lo)
    uint2* Bs2  = As2 + 16 * 132;                // [16][132] (hi,lo)
    int*   tok2 = (int*)(Bs2 + 16 * 132);        // [128]
    int*   xprog = tok2 + 128;
    ull*   hsmu = (ull*)hsm;

    const int bx  = blockIdx.x;
    const int dir = bx & 1;
    const int ks  = (bx >> 1) & 7;
    const int bt  = bx >> 4;
    const int k0s = ks * 32;
    const int b0  = bt * 8;
    const int tid = threadIdx.x;
    const int grp = bt * 2 + dir;

    const float* __restrict__ Whh  = dir ? Wb_hh : Wf_hh;
    const float* __restrict__ Wih  = dir ? Wb_ih : Wf_ih;
    const float* __restrict__ bias = dir ? bb    : bf;

    // one-time init (all 384 threads)
    for (int i = tid; i < 128 * 128; i += 384) {
        int r = i >> 7;
        int j = i & 127;
        int g = r >> 5, kl = r & 31;
        ull v = *(const ull*)(Whh + (size_t)(g * 256 + k0s + kl) * HDIM + 2 * j);
        Wp[(g * 128 + j) * 33 + kl] = v;
    }
    for (int i = tid; i < 2048; i += 384) hsm[i] = 0.f;   // h(-1)=0
    if (tid == 0) *xprog = 0;
    __syncthreads();

    if (tid >= 256) {
        // ================= LSTM half (warps 8-11) =========
        const int ltid = tid - 256;        // 0..127
        const int lane = ltid & 31;
        const int warp = ltid >> 5;        // 0..3
        const int bA   = warp * 2;

        int* myflag = &g_flagsB[(((grp * 8) + ks) * 4 + warp) * 32];
        int* prodflags = lane < 8
            ? &g_flagsB[(((grp * 8) + (warp * 2 + (lane >> 2))) * 4 + (lane & 3)) * 32]
            : &g_flagsB[(((grp * 8) + warp * 2) * 4) * 32];

        const int base = *(volatile int*)myflag;

        const size_t ctaX = ((size_t)((dir * 8 + bt) * 8 + ks)) * (TT * 1024);
        const float* xmeA = g_X + ctaX + bA * 128 + lane;
        const float* xmeB = g_X + ctaX + (bA + 1) * 128 + lane;
        const size_t grpH = ((size_t)(dir * 8 + bt)) * (TT * 8 * HDIM);
        float* hmeA = g_h + grpH + bA * HDIM + (k0s + lane);
        float* hmeB = g_h + grpH + (bA + 1) * HDIM + (k0s + lane);
        const float* hsrc = g_h + grpH + (lane >> 2) * HDIM + warp * 64 + (lane & 3) * 16;
        float* hdst = hsm + warp * 512 + (lane >> 2) * 64 + (lane & 3) * 16;

        float cA = 0.f, cB = 0.f;
        int xseen = 0;

        for (int t = 0; t < TT; t++) {
            if (t > 0) {
                const int target = base + t;
                int fv = 0;
                bool done;
                do {
                    if (lane < 8)
                        asm volatile("ld.acquire.gpu.global.b32 %0, [%1];"
                                     : "=r"(fv) : "l"(prodflags) : "memory");
                    done = __all_sync(0xffffffffu, (lane >= 8) || (fv >= target));
                } while (!done);
                __syncwarp();

                const float* src = hsrc + (size_t)(t - 1) * (8 * HDIM);
                float4 v0 = *(const float4*)src;
                float4 v1 = *(const float4*)(src + 4);
                float4 v2 = *(const float4*)(src + 8);
                float4 v3 = *(const float4*)(src + 12);
                *(float4*)hdst        = v0;
                *(float4*)(hdst + 4)  = v1;
                *(float4*)(hdst + 8)  = v2;
                *(float4*)(hdst + 12) = v3;
                __syncwarp();
            }

            // cached xprog poll (only hits L2 when needed)
            if (xseen < t + 1) {
                int xv;
                do {
                    asm volatile("ld.acquire.cta.b32 %0, [%1];" : "=r"(xv) : "l"(xprog) : "memory");
                } while (xv < t + 1);
                xseen = xv;
            }

            const float* xrA = xmeA + (size_t)t * 1024;
            const float* xrB = xmeB + (size_t)t * 1024;
            float xiA = xrA[0], xfA = xrA[32], xgA = xrA[64], xoA = xrA[96];
            float xiB = xrB[0], xfB = xrB[32], xgB = xrB[64], xoB = xrB[96];

            ull acc[4][8];
#pragma unroll
            for (int g = 0; g < 4; g++)
#pragma unroll
                for (int b = 0; b < 8; b++) acc[g][b] = 0ull;

            const ull* hW = hsmu + warp * 256;   // [8b][32 kk-pairs]
            const int kkb = warp * 32;
#pragma unroll 2
            for (int c2 = 0; c2 < 16; c2++) {
                int kk2 = kkb + 2 * c2;
                ull w0a = Wp[(0 * 128 + kk2) * 33 + lane];
                ull w0b = Wp[(0 * 128 + kk2 + 1) * 33 + lane];
                ull w1a = Wp[(1 * 128 + kk2) * 33 + lane];
                ull w1b = Wp[(1 * 128 + kk2 + 1) * 33 + lane];
                ull w2a = Wp[(2 * 128 + kk2) * 33 + lane];
                ull w2b = Wp[(2 * 128 + kk2 + 1) * 33 + lane];
                ull w3a = Wp[(3 * 128 + kk2) * 33 + lane];
                ull w3b = Wp[(3 * 128 + kk2 + 1) * 33 + lane];
#pragma unroll
                for (int b = 0; b < 8; b++) {
                    ulonglong2 h01 = *(const ulonglong2*)&hW[b * 32 + 2 * c2];
                    acc[0][b] = ffma2(h01.x, w0a, acc[0][b]);
                    acc[0][b] = ffma2(h01.y, w0b, acc[0][b]);
                    acc[1][b] = ffma2(h01.x, w1a, acc[1][b]);
                    acc[1][b] = ffma2(h01.y, w1b, acc[1][b]);
                    acc[2][b] = ffma2(h01.x, w2a, acc[2][b]);
                    acc[2][b] = ffma2(h01.y, w2b, acc[2][b]);
                    acc[3][b] = ffma2(h01.x, w3a, acc[3][b]);
                    acc[3][b] = ffma2(h01.y, w3b, acc[3][b]);
                }
            }

            float* pb = ps + (t & 1) * 4096;
#pragma unroll
            for (int g = 0; g < 4; g++)
#pragma unroll
                for (int b = 0; b < 8; b++) {
                    float2 s = u2f2(acc[g][b]);
                    pb[((warp * 4 + g) * 8 + b) * 32 + lane] = s.x + s.y;
                }
            BARL();

            float sA0 = 0.f, sA1 = 0.f, sA2 = 0.f, sA3 = 0.f;
            float sB0 = 0.f, sB1 = 0.f, sB2 = 0.f, sB3 = 0.f;
#pragma unroll
            for (int w = 0; w < 4; w++) {
                sA0 += pb[((w * 4 + 0) * 8 + bA) * 32 + lane];
                sA1 += pb[((w * 4 + 1) * 8 + bA) * 32 + lane];
                sA2 += pb[((w * 4 + 2) * 8 + bA) * 32 + lane];
                sA3 += pb[((w * 4 + 3) * 8 + bA) * 32 + lane];
                sB0 += pb[((w * 4 + 0) * 8 + bA + 1) * 32 + lane];
                sB1 += pb[((w * 4 + 1) * 8 + bA + 1) * 32 + lane];
                sB2 += pb[((w * 4 + 2) * 8 + bA + 1) * 32 + lane];
                sB3 += pb[((w * 4 + 3) * 8 + bA + 1) * 32 + lane];
            }
            float giA = xiA + sA0, gfA = xfA + sA1, ggA = xgA + sA2, goA = xoA + sA3;
            float giB = xiB + sB0, gfB = xfB + sB1, ggB = xgB + sB2, goB = xoB + sB3;

            cA = sigf(gfA) * cA + sigf(giA) * tanhf(ggA);
            float hA = sigf(goA) * tanhf(cA);
            cB = sigf(gfB) * cB + sigf(giB) * tanhf(ggB);
            float hB = sigf(goB) * tanhf(cB);
            hmeA[(size_t)t * (8 * HDIM)] = hA;
            hmeB[(size_t)t * (8 * HDIM)] = hB;

            if (t + 1 < TT) {
                __syncwarp();
                if (lane == 0)
                    asm volatile("st.release.gpu.global.b32 [%0], %1;"
                                 :: "l"(myflag), "r"(base + t + 1) : "memory");
            }
        }
    } else {
        // ===== GEMM half (warps 0-7): tf32 mma, hi/lo pre-staged =========
        const int tid2 = tid;              // 0..255
        const int gw   = tid2 >> 5;        // warp 0..7
        const int lane = tid2 & 31;
        const int m0w  = (gw >> 2) * 64;
        const int wn   = gw & 3;
        const int n0w  = wn * 32;
        const int groupID = lane >> 2;     // 0..7
        const int tig     = lane & 3;      // 0..3
        const int lrow = tid2 >> 1;        // staging row 0..127
        const int kc8  = (tid2 & 1) * 8;
        const size_t xbase = ((size_t)((dir * 8 + bt) * 8 + ks)) * (TT * 1024);

        float bb0[4], bb1[4];
#pragma unroll
        for (int ni = 0; ni < 4; ni++) {
            int kl = ni * 8 + tig * 2;
            bb0[ni] = bias[wn * 256 + k0s + kl];
            bb1[ni] = bias[wn * 256 + k0s + kl + 1];
        }

        for (int mt = 0; mt < 32; mt++) {
            if (tid2 < 128) {
                int tloc = tid2 >> 3, b_l = tid2 & 7;
                int t = mt * 16 + tloc, b = b0 + b_l;
                int tt = t;
                if (dir) { int len = lengths[b]; tt = (t < len) ? (len - 1 - t) : t; }
                tok2[tid2] = sentence[b * TT + tt];
            }
            BARG();

            const float* erow = emb + (size_t)tok2[lrow] * EE;
            const float* wrow = Wih + (size_t)((lrow >> 5) * 256 + k0s + (lrow & 31)) * EE;

            float acc[4][4][4];
#pragma unroll
            for (int mi = 0; mi < 4; mi++)
#pragma unroll
                for (int ni = 0; ni < 4; ni++)
#pragma unroll
                    for (int j = 0; j < 4; j++) acc[mi][ni][j] = 0.f;

            for (int k0 = 0; k0 < 304; k0 += 16) {
                const int kb = k0 + kc8;
                // stage A/B as (hi,lo) tf32 pairs — convert ONCE here
                if (kb + 8 <= EE) {
                    float4 v0 = *(const float4*)(erow + kb);
                    float4 v1 = *(const float4*)(erow + kb + 4);
                    As2[(kc8 + 0) * 132 + lrow] = tf32pair(v0.x);
                    As2[(kc8 + 1) * 132 + lrow] = tf32pair(v0.y);
                    As2[(kc8 + 2) * 132 + lrow] = tf32pair(v0.z);
                    As2[(kc8 + 3) * 132 + lrow] = tf32pair(v0.w);
                    As2[(kc8 + 4) * 132 + lrow] = tf32pair(v1.x);
                    As2[(kc8 + 5) * 132 + lrow] = tf32pair(v1.y);
                    As2[(kc8 + 6) * 132 + lrow] = tf32pair(v1.z);
                    As2[(kc8 + 7) * 132 + lrow] = tf32pair(v1.w);
                } else {
#pragma unroll
                    for (int i = 0; i < 8; i++)
                        As2[(kc8 + i) * 132 + lrow] =
                            tf32pair((kb + i < EE) ? erow[kb + i] : 0.f);
                }
                if (kb + 8 <= EE) {
                    float4 v0 = *(const float4*)(wrow + kb);
                    float4 v1 = *(const float4*)(wrow + kb + 4);
                    Bs2[(kc8 + 0) * 132 + lrow] = tf32pair(v0.x);
                    Bs2[(kc8 + 1) * 132 + lrow] = tf32pair(v0.y);
                    Bs2[(kc8 + 2) * 132 + lrow] = tf32pair(v0.z);
                    Bs2[(kc8 + 3) * 132 + lrow] = tf32pair(v0.w);
                    Bs2[(kc8 + 4) * 132 + lrow] = tf32pair(v1.x);
                    Bs2[(kc8 + 5) * 132 + lrow] = tf32pair(v1.y);
                    Bs2[(kc8 + 6) * 132 + lrow] = tf32pair(v1.z);
                    Bs2[(kc8 + 7) * 132 + lrow] = tf32pair(v1.w);
                } else {
#pragma unroll
                    for (int i = 0; i < 8; i++)
                        Bs2[(kc8 + i) * 132 + lrow] =
                            tf32pair((kb + i < EE) ? wrow[kb + i] : 0.f);
                }
                BARG();

#pragma unroll
                for (int k8 = 0; k8 < 16; k8 += 8) {
                    const uint2* Ak  = As2 + (k8 + tig) * 132;
                    const uint2* Ak4 = As2 + (k8 + tig + 4) * 132;
                    unsigned ahi[4][4], alo[4][4];
#pragma unroll
                    for (int mi = 0; mi < 4; mi++) {
                        int mr = m0w + mi * 16 + groupID;
                        uint2 e0 = Ak[mr],  e1 = Ak[mr + 8];
                        uint2 e2 = Ak4[mr], e3 = Ak4[mr + 8];
                        ahi[mi][0] = e0.x; alo[mi][0] = e0.y;
                        ahi[mi][1] = e1.x; alo[mi][1] = e1.y;
                        ahi[mi][2] = e2.x; alo[mi][2] = e2.y;
                        ahi[mi][3] = e3.x; alo[mi][3] = e3.y;
                    }
                    const uint2* Bk  = Bs2 + (k8 + tig) * 132;
                    const uint2* Bk4 = Bs2 + (k8 + tig + 4) * 132;
                    unsigned bhi[4][2], blo[4][2];
#pragma unroll
                    for (int ni = 0; ni < 4; ni++) {
                        int nc = n0w + ni * 8 + groupID;
                        uint2 f0 = Bk[nc], f1 = Bk4[nc];
                        bhi[ni][0] = f0.x; blo[ni][0] = f0.y;
                        bhi[ni][1] = f1.x; blo[ni][1] = f1.y;
                    }
#pragma unroll
                    for (int mi = 0; mi < 4; mi++)
#pragma unroll
                        for (int ni = 0; ni < 4; ni++) {
                            MMA_TF32(acc[mi][ni], ahi[mi], bhi[ni]);
                            MMA_TF32(acc[mi][ni], ahi[mi], blo[ni]);
                            MMA_TF32(acc[mi][ni], alo[mi], bhi[ni]);
                        }
                }
                BARG();
            }

            // epilogue
#pragma unroll
            for (int mi = 0; mi < 4; mi++) {
                int r0 = m0w + mi * 16 + groupID;
                int tl0 = r0 >> 3,        bl0 = r0 & 7;
                int tl1 = (r0 + 8) >> 3,  bl1 = (r0 + 8) & 7;
                size_t o0 = xbase + (size_t)(mt * 16 + tl0) * 1024 + bl0 * 128;
                size_t o1 = xbase + (size_t)(mt * 16 + tl1) * 1024 + bl1 * 128;
#pragma unroll
                for (int ni = 0; ni < 4; ni++) {
                    int nc = n0w + ni * 8 + tig * 2;
                    float2 v;
                    v.x = acc[mi][ni][0] + bb0[ni];
                    v.y = acc[mi][ni][1] + bb1[ni];
                    *(float2*)&g_X[o0 + nc] = v;
                    v.x = acc[mi][ni][2] + bb0[ni];
                    v.y = acc[mi][ni][3] + bb1[ni];
                    *(float2*)&g_X[o1 + nc] = v;
                }
            }
            BARG();
            if (tid2 == 0) {
                int val = (mt + 1) * 16;
                asm volatile("st.release.cta.b32 [%0], %1;" :: "l"(xprog), "r"(val) : "memory");
            }
        }
    }
}

// =====================================================================
// Kernel 3: emissions (unchanged)
// =====================================================================
__global__ void emis_kernel(const int* __restrict__ lengths,
                            const float* __restrict__ W_out,
                            const float* __restrict__ b_out)
{
    __shared__ float Wsm[KTAG * 2 * HDIM];
    __shared__ float bsm[KTAG];

    const int tid = threadIdx.x;
    for (int i = tid; i < KTAG * 2 * HDIM; i += 256) Wsm[i] = W_out[i];
    if (tid < KTAG) bsm[tid] = b_out[tid];
    __syncthreads();

    const int warp = tid >> 5;
    const int lane = tid & 31;
    const int r = blockIdx.x * 8 + warp;
    const int b = r >> 9;
    const int t = r & 511;
    const int len = lengths[b];
    const int tr  = (t < len) ? (len - 1 - t) : t;
    const int bt = b >> 3, b_l = b & 7;

    const float* hf = g_h + ((size_t)(0 * 8 + bt)) * (TT * 8 * HDIM)
                          + (size_t)t  * (8 * HDIM) + b_l * HDIM;
    const float* hb = g_h + ((size_t)(1 * 8 + bt)) * (TT * 8 * HDIM)
                          + (size_t)tr * (8 * HDIM) + b_l * HDIM;

    float x[16];
#pragma unroll
    for (int i = 0; i < 8; i++) x[i]     = hf[lane + 32 * i];
#pragma unroll
    for (int i = 0; i < 8; i++) x[8 + i] = hb[lane + 32 * i];

    for (int kk = 0; kk < KTAG; kk++) {
        const float* w = Wsm + (size_t)kk * (2 * HDIM);
        float s = 0.f;
#pragma unroll
        for (int i = 0; i < 8; i++) s += x[i]     * w[lane + 32 * i];
#pragma unroll
        for (int i = 0; i < 8; i++) s += x[8 + i] * w[HDIM + lane + 32 * i];
#pragma unroll
        for (int off = 16; off; off >>= 1) s += __shfl_xor_sync(0xffffffffu, s, off);
        if (lane == 0) g_emis[((size_t)b * TT + t) * KTAG + kk] = s + bsm[kk];
    }
}

// =====================================================================
// Kernel 4: Viterbi (unchanged)
// =====================================================================
#define VIT_SMEM 53248
#define VCOMB(av, ai_, bv, bi_) { if ((bv) > (av)) { (av) = (bv); (ai_) = (bi_); } }

__global__ void viterbi_kernel(const int* __restrict__ lengths,
                               const int* __restrict__ stop_id_p,
                               const float* __restrict__ trans,
                               float* __restrict__ out)
{
    extern __shared__ char vsm[];
    float* emis_s = (float*)vsm;
    float* trp    = emis_s + TT * KTAG;
    float* term   = trp + KTAG * 21;
    unsigned char* bp = (unsigned char*)(term + KTAG);

    const int b = blockIdx.x;
    const int lane = threadIdx.x;

    for (int i = lane; i < TT * KTAG; i += 32)
        emis_s[i] = g_emis[(size_t)b * TT * KTAG + i];
    for (int i = lane; i < KTAG * KTAG; i += 32)
        trp[(i / KTAG) * 21 + (i % KTAG)] = trans[i];
    __syncwarp();

    const int len  = lengths[b];
    const int stop = *stop_id_p;
    const float* trl = trp + (lane < KTAG ? lane : 0) * 21;

    float d = 0.f;

    for (int t = 0; t < TT; t++) {
        float em = (lane < KTAG) ? emis_s[t * KTAG + lane] : 0.f;

        float v[KTAG];
#pragma unroll
        for (int p = 0; p < KTAG; p++)
            v[p] = __shfl_sync(0xffffffffu, d, p) + trl[p];

        float w10[10]; int i10[10];
#pragma unroll
        for (int i = 0; i < 10; i++) {
            w10[i] = v[2 * i]; i10[i] = 2 * i;
            VCOMB(w10[i], i10[i], v[2 * i + 1], 2 * i + 1);
        }
        float w5[5]; int i5[5];
#pragma unroll
        for (int i = 0; i < 5; i++) {
            w5[i] = w10[2 * i]; i5[i] = i10[2 * i];
            VCOMB(w5[i], i5[i], w10[2 * i + 1], i10[2 * i + 1]);
        }
        float bv0 = w5[0]; int bi0 = i5[0];
        VCOMB(bv0, bi0, w5[1], i5[1]);
        float bv1 = w5[2]; int bi1 = i5[2];
        VCOMB(bv1, bi1, w5[3], i5[3]);
        VCOMB(bv0, bi0, bv1, bi1);
        VCOMB(bv0, bi0, w5[4], i5[4]);

        bool valid = (t < len);
        if (lane < KTAG) {
            float nd = bv0 + em;
            int bpv  = valid ? bi0 : lane;
            d = valid ? nd : d;
            bp[t * KTAG + lane] = (unsigned char)bpv;
        }
    }

    if (lane < KTAG) term[lane] = d + trp[stop * 21 + lane];
    __syncwarp();

    if (lane == 0) {
        float best = -3.4e38f; int arg = 0;
        for (int j = 0; j < KTAG; j++)
            if (term[j] > best) { best = term[j]; arg = j; }
        out[b] = best;
        float* po = out + BB + (size_t)b * (TT + 1);
        po[TT] = (float)arg;
        int tag = arg;
        for (int t = TT - 1; t >= 0; t--) {
            tag = bp[t * KTAG + tag];
            po[t] = (float)tag;
        }
    }
}

// =====================================================================
// launch
// =====================================================================
extern "C" void kernel_launch(void* const* d_in, const int* in_sizes, int n_in,
                              void* d_out, int out_size)
{
    (void)in_sizes; (void)n_in; (void)out_size;
    const int*   sentence = (const int*)d_in[0];
    const int*   lengths  = (const int*)d_in[1];
    const int*   stop_id  = (const int*)d_in[3];
    const float* emb      = (const float*)d_in[4];
    const float* Wf_ih    = (const float*)d_in[5];
    const float* Wf_hh    = (const float*)d_in[6];
    const float* bf       = (const float*)d_in[7];
    const float* Wb_ih    = (const float*)d_in[8];
    const float* Wb_hh    = (const float*)d_in[9];
    const float* bb       = (const float*)d_in[10];
    const float* W_out    = (const float*)d_in[11];
    const float* b_out    = (const float*)d_in[12];
    const float* trans    = (const float*)d_in[13];
    float* out = (float*)d_out;

    static int attr_set = 0;
    if (!attr_set) {
        cudaFuncSetAttribute(fused_persistent_kernel,
                             cudaFuncAttributeMaxDynamicSharedMemorySize, SMEM_FUSED);
        cudaFuncSetAttribute(viterbi_kernel,
                             cudaFuncAttributeMaxDynamicSharedMemorySize, VIT_SMEM);
        attr_set = 1;
    }

    fused_persistent_kernel<<<GRID_P, 384, SMEM_FUSED>>>(
        sentence, lengths, emb, Wf_ih, bf, Wb_ih, bb, Wf_hh, Wb_hh);

    emis_kernel<<<BB * TT / 8, 256>>>(lengths, W_out, b_out);

    viterbi_kernel<<<BB, 32, VIT_SMEM>>>(lengths, stop_id, trans, out);
}

// round 17
// speedup vs baseline: 1.6797x; 1.6797x over previous
#include <cuda_runtime.h>
#include <math.h>

// Problem constants
#define BB   64
#define TT   512
#define EE   300
#define HDIM 256
#define G4   1024
#define KTAG 20
#define GRID_P 128

typedef unsigned long long ull;

// ---------------- scratch ----------------
// g_X blocked: [dir][bt][ks][t][b_l][gate][k_l]
__device__ float g_X[(size_t)2 * BB * TT * G4];
// g_h blocked: [dir][bt][t][b_l][k]
__device__ float g_h[(size_t)2 * BB * TT * HDIM];
__device__ float g_emis[(size_t)BB * TT * KTAG];
// per-(group, producerCTA, producerWarp[4]) monotone flags, 128B apart
__device__ int   g_flagsB[16 * 8 * 4 * 32];

// ---------------- packed fp32x2 helpers ----------------
__device__ __forceinline__ ull ffma2(ull a, ull b, ull c) {
    ull d;
    asm("fma.rn.f32x2 %0, %1, %2, %3;" : "=l"(d) : "l"(a), "l"(b), "l"(c));
    return d;
}
__device__ __forceinline__ float2 u2f2(ull v) {
    float2 f;
    asm("mov.b64 {%0, %1}, %2;" : "=f"(f.x), "=f"(f.y) : "l"(v));
    return f;
}
// ---------------- tf32 helpers ----------------
__device__ __forceinline__ unsigned tf32hi(float x) {
    unsigned r;
    asm("cvt.rna.tf32.f32 %0, %1;" : "=r"(r) : "f"(x));
    return r;
}
__device__ __forceinline__ unsigned tf32cv(float x) {
    unsigned r;
    asm("cvt.rna.tf32.f32 %0, %1;" : "=r"(r) : "f"(x));
    return r;
}
#define MMA_TF32(c, a, b) \
    asm volatile("mma.sync.aligned.m16n8k8.row.col.f32.tf32.tf32.f32 " \
        "{%0,%1,%2,%3}, {%4,%5,%6,%7}, {%8,%9}, {%0,%1,%2,%3};" \
        : "+f"((c)[0]), "+f"((c)[1]), "+f"((c)[2]), "+f"((c)[3]) \
        : "r"((a)[0]), "r"((a)[1]), "r"((a)[2]), "r"((a)[3]), \
          "r"((b)[0]), "r"((b)[1]))

#define BARL() asm volatile("bar.sync 4, 128;" ::: "memory")
#define BARG() asm volatile("bar.sync 5, 256;" ::: "memory")

__device__ __forceinline__ float sigf(float x) { return 1.f / (1.f + expf(-x)); }

// =====================================================================
// FUSED persistent kernel: 128 CTAs x 384 threads.  (R15 + cached xprog)
//   warps 0-7  (tid 0..255)   : gates GEMM on TENSOR pipe
//                               (mma.sync m16n8k8 tf32, 3xTF32 split)
//   warps 8-11 (tid 256..383) : LSTM (1/SMSP, HIGH wid priority)
// =====================================================================
#define WP_ULL (4 * 128 * 33)
// Wp 135168 | hsm 8192 | ps 32768 | As 8448 | Bs 8448 | tok 512 | xprog 128
#define SMEM_FUSED 193664

__global__ void __launch_bounds__(384, 1)
fused_persistent_kernel(const int* __restrict__ sentence,
                        const int* __restrict__ lengths,
                        const float* __restrict__ emb,
                        const float* __restrict__ Wf_ih,
                        const float* __restrict__ bf,
                        const float* __restrict__ Wb_ih,
                        const float* __restrict__ bb,
                        const float* __restrict__ Wf_hh,
                        const float* __restrict__ Wb_hh)
{
    extern __shared__ char smraw[];
    ull*   Wp   = (ull*)smraw;                   // [4][128][33]
    float* hsm  = (float*)(Wp + WP_ULL);         // 4 warps x [8b][64k]
    float* ps   = hsm + 2048;                    // [2][4][4][8][32] psum
    float* As   = ps + 8192;                     // [16][132]
    float* Bs   = As + 16 * 132;                 // [16][132]
    int*   tok2 = (int*)(Bs + 16 * 132);         // [128]
    int*   xprog = tok2 + 128;
    ull*   hsmu = (ull*)hsm;

    const int bx  = blockIdx.x;
    const int dir = bx & 1;
    const int ks  = (bx >> 1) & 7;
    const int bt  = bx >> 4;
    const int k0s = ks * 32;
    const int b0  = bt * 8;
    const int tid = threadIdx.x;
    const int grp = bt * 2 + dir;

    const float* __restrict__ Whh  = dir ? Wb_hh : Wf_hh;
    const float* __restrict__ Wih  = dir ? Wb_ih : Wf_ih;
    const float* __restrict__ bias = dir ? bb    : bf;

    // one-time init (all 384 threads)
    for (int i = tid; i < 128 * 128; i += 384) {
        int r = i >> 7;
        int j = i & 127;
        int g = r >> 5, kl = r & 31;
        ull v = *(const ull*)(Whh + (size_t)(g * 256 + k0s + kl) * HDIM + 2 * j);
        Wp[(g * 128 + j) * 33 + kl] = v;
    }
    for (int i = tid; i < 2048; i += 384) hsm[i] = 0.f;   // h(-1)=0
    if (tid == 0) *xprog = 0;
    __syncthreads();

    if (tid >= 256) {
        // ================= LSTM half (warps 8-11) =====
        const int ltid = tid - 256;        // 0..127
        const int lane = ltid & 31;
        const int warp = ltid >> 5;        // 0..3
        const int bA   = warp * 2;

        int* myflag = &g_flagsB[(((grp * 8) + ks) * 4 + warp) * 32];
        int* prodflags = lane < 8
            ? &g_flagsB[(((grp * 8) + (warp * 2 + (lane >> 2))) * 4 + (lane & 3)) * 32]
            : &g_flagsB[(((grp * 8) + warp * 2) * 4) * 32];

        const int base = *(volatile int*)myflag;

        const size_t ctaX = ((size_t)((dir * 8 + bt) * 8 + ks)) * (TT * 1024);
        const float* xmeA = g_X + ctaX + bA * 128 + lane;
        const float* xmeB = g_X + ctaX + (bA + 1) * 128 + lane;
        const size_t grpH = ((size_t)(dir * 8 + bt)) * (TT * 8 * HDIM);
        float* hmeA = g_h + grpH + bA * HDIM + (k0s + lane);
        float* hmeB = g_h + grpH + (bA + 1) * HDIM + (k0s + lane);
        const float* hsrc = g_h + grpH + (lane >> 2) * HDIM + warp * 64 + (lane & 3) * 16;
        float* hdst = hsm + warp * 512 + (lane >> 2) * 64 + (lane & 3) * 16;

        float cA = 0.f, cB = 0.f;
        int xseen = 0;

        for (int t = 0; t < TT; t++) {
            if (t > 0) {
                const int target = base + t;
                int fv = 0;
                bool done;
                do {
                    if (lane < 8)
                        asm volatile("ld.acquire.gpu.global.b32 %0, [%1];"
                                     : "=r"(fv) : "l"(prodflags) : "memory");
                    done = __all_sync(0xffffffffu, (lane >= 8) || (fv >= target));
                } while (!done);
                __syncwarp();

                const float* src = hsrc + (size_t)(t - 1) * (8 * HDIM);
                float4 v0 = *(const float4*)src;
                float4 v1 = *(const float4*)(src + 4);
                float4 v2 = *(const float4*)(src + 8);
                float4 v3 = *(const float4*)(src + 12);
                *(float4*)hdst        = v0;
                *(float4*)(hdst + 4)  = v1;
                *(float4*)(hdst + 8)  = v2;
                *(float4*)(hdst + 12) = v3;
                __syncwarp();
            }

            // cached xprog poll: only hit L2 when cache is stale
            if (xseen < t + 1) {
                int xv;
                do {
                    asm volatile("ld.acquire.cta.b32 %0, [%1];" : "=r"(xv) : "l"(xprog) : "memory");
                } while (xv < t + 1);
                xseen = xv;
            }

            const float* xrA = xmeA + (size_t)t * 1024;
            const float* xrB = xmeB + (size_t)t * 1024;
            float xiA = xrA[0], xfA = xrA[32], xgA = xrA[64], xoA = xrA[96];
            float xiB = xrB[0], xfB = xrB[32], xgB = xrB[64], xoB = xrB[96];

            ull acc[4][8];
#pragma unroll
            for (int g = 0; g < 4; g++)
#pragma unroll
                for (int b = 0; b < 8; b++) acc[g][b] = 0ull;

            const ull* hW = hsmu + warp * 256;   // [8b][32 kk-pairs]
            const int kkb = warp * 32;
#pragma unroll 2
            for (int c2 = 0; c2 < 16; c2++) {
                int kk2 = kkb + 2 * c2;
                ull w0a = Wp[(0 * 128 + kk2) * 33 + lane];
                ull w0b = Wp[(0 * 128 + kk2 + 1) * 33 + lane];
                ull w1a = Wp[(1 * 128 + kk2) * 33 + lane];
                ull w1b = Wp[(1 * 128 + kk2 + 1) * 33 + lane];
                ull w2a = Wp[(2 * 128 + kk2) * 33 + lane];
                ull w2b = Wp[(2 * 128 + kk2 + 1) * 33 + lane];
                ull w3a = Wp[(3 * 128 + kk2) * 33 + lane];
                ull w3b = Wp[(3 * 128 + kk2 + 1) * 33 + lane];
#pragma unroll
                for (int b = 0; b < 8; b++) {
                    ulonglong2 h01 = *(const ulonglong2*)&hW[b * 32 + 2 * c2];
                    acc[0][b] = ffma2(h01.x, w0a, acc[0][b]);
                    acc[0][b] = ffma2(h01.y, w0b, acc[0][b]);
                    acc[1][b] = ffma2(h01.x, w1a, acc[1][b]);
                    acc[1][b] = ffma2(h01.y, w1b, acc[1][b]);
                    acc[2][b] = ffma2(h01.x, w2a, acc[2][b]);
                    acc[2][b] = ffma2(h01.y, w2b, acc[2][b]);
                    acc[3][b] = ffma2(h01.x, w3a, acc[3][b]);
                    acc[3][b] = ffma2(h01.y, w3b, acc[3][b]);
                }
            }

            float* pb = ps + (t & 1) * 4096;
#pragma unroll
            for (int g = 0; g < 4; g++)
#pragma unroll
                for (int b = 0; b < 8; b++) {
                    float2 s = u2f2(acc[g][b]);
                    pb[((warp * 4 + g) * 8 + b) * 32 + lane] = s.x + s.y;
                }
            BARL();

            float sA0 = 0.f, sA1 = 0.f, sA2 = 0.f, sA3 = 0.f;
            float sB0 = 0.f, sB1 = 0.f, sB2 = 0.f, sB3 = 0.f;
#pragma unroll
            for (int w = 0; w < 4; w++) {
                sA0 += pb[((w * 4 + 0) * 8 + bA) * 32 + lane];
                sA1 += pb[((w * 4 + 1) * 8 + bA) * 32 + lane];
                sA2 += pb[((w * 4 + 2) * 8 + bA) * 32 + lane];
                sA3 += pb[((w * 4 + 3) * 8 + bA) * 32 + lane];
                sB0 += pb[((w * 4 + 0) * 8 + bA + 1) * 32 + lane];
                sB1 += pb[((w * 4 + 1) * 8 + bA + 1) * 32 + lane];
                sB2 += pb[((w * 4 + 2) * 8 + bA + 1) * 32 + lane];
                sB3 += pb[((w * 4 + 3) * 8 + bA + 1) * 32 + lane];
            }
            float giA = xiA + sA0, gfA = xfA + sA1, ggA = xgA + sA2, goA = xoA + sA3;
            float giB = xiB + sB0, gfB = xfB + sB1, ggB = xgB + sB2, goB = xoB + sB3;

            cA = sigf(gfA) * cA + sigf(giA) * tanhf(ggA);
            float hA = sigf(goA) * tanhf(cA);
            cB = sigf(gfB) * cB + sigf(giB) * tanhf(ggB);
            float hB = sigf(goB) * tanhf(cB);
            hmeA[(size_t)t * (8 * HDIM)] = hA;
            hmeB[(size_t)t * (8 * HDIM)] = hB;

            if (t + 1 < TT) {
                __syncwarp();
                if (lane == 0)
                    asm volatile("st.release.gpu.global.b32 [%0], %1;"
                                 :: "l"(myflag), "r"(base + t + 1) : "memory");
            }
        }
    } else {
        // ===== GEMM half (warps 0-7): tensor-pipe tf32, 3xTF32 (R15) =====
        const int tid2 = tid;              // 0..255
        const int gw   = tid2 >> 5;        // warp 0..7
        const int lane = tid2 & 31;
        const int m0w  = (gw >> 2) * 64;
        const int wn   = gw & 3;
        const int n0w  = wn * 32;
        const int groupID = lane >> 2;     // 0..7
        const int tig     = lane & 3;      // 0..3
        const int lrow = tid2 >> 1;        // staging row 0..127
        const int kc8  = (tid2 & 1) * 8;
        const size_t xbase = ((size_t)((dir * 8 + bt) * 8 + ks)) * (TT * 1024);

        float bb0[4], bb1[4];
#pragma unroll
        for (int ni = 0; ni < 4; ni++) {
            int kl = ni * 8 + tig * 2;
            bb0[ni] = bias[wn * 256 + k0s + kl];
            bb1[ni] = bias[wn * 256 + k0s + kl + 1];
        }

        for (int mt = 0; mt < 32; mt++) {
            if (tid2 < 128) {
                int tloc = tid2 >> 3, b_l = tid2 & 7;
                int t = mt * 16 + tloc, b = b0 + b_l;
                int tt = t;
                if (dir) { int len = lengths[b]; tt = (t < len) ? (len - 1 - t) : t; }
                tok2[tid2] = sentence[b * TT + tt];
            }
            BARG();

            const float* erow = emb + (size_t)tok2[lrow] * EE;
            const float* wrow = Wih + (size_t)((lrow >> 5) * 256 + k0s + (lrow & 31)) * EE;

            float acc[4][4][4];
#pragma unroll
            for (int mi = 0; mi < 4; mi++)
#pragma unroll
                for (int ni = 0; ni < 4; ni++)
#pragma unroll
                    for (int j = 0; j < 4; j++) acc[mi][ni][j] = 0.f;

            for (int k0 = 0; k0 < 304; k0 += 16) {
                const int kb = k0 + kc8;
                if (kb + 8 <= EE) {
                    float4 v0 = *(const float4*)(erow + kb);
                    float4 v1 = *(const float4*)(erow + kb + 4);
                    As[(kc8 + 0) * 132 + lrow] = v0.x;
                    As[(kc8 + 1) * 132 + lrow] = v0.y;
                    As[(kc8 + 2) * 132 + lrow] = v0.z;
                    As[(kc8 + 3) * 132 + lrow] = v0.w;
                    As[(kc8 + 4) * 132 + lrow] = v1.x;
                    As[(kc8 + 5) * 132 + lrow] = v1.y;
                    As[(kc8 + 6) * 132 + lrow] = v1.z;
                    As[(kc8 + 7) * 132 + lrow] = v1.w;
                } else {
#pragma unroll
                    for (int i = 0; i < 8; i++)
                        As[(kc8 + i) * 132 + lrow] = (kb + i < EE) ? erow[kb + i] : 0.f;
                }
                if (kb + 8 <= EE) {
                    float4 v0 = *(const float4*)(wrow + kb);
                    float4 v1 = *(const float4*)(wrow + kb + 4);
                    Bs[(kc8 + 0) * 132 + lrow] = v0.x;
                    Bs[(kc8 + 1) * 132 + lrow] = v0.y;
                    Bs[(kc8 + 2) * 132 + lrow] = v0.z;
                    Bs[(kc8 + 3) * 132 + lrow] = v0.w;
                    Bs[(kc8 + 4) * 132 + lrow] = v1.x;
                    Bs[(kc8 + 5) * 132 + lrow] = v1.y;
                    Bs[(kc8 + 6) * 132 + lrow] = v1.z;
                    Bs[(kc8 + 7) * 132 + lrow] = v1.w;
                } else {
#pragma unroll
                    for (int i = 0; i < 8; i++)
                        Bs[(kc8 + i) * 132 + lrow] = (kb + i < EE) ? wrow[kb + i] : 0.f;
                }
                BARG();

#pragma unroll
                for (int k8 = 0; k8 < 16; k8 += 8) {
                    const float* Ak  = As + (k8 + tig) * 132;
                    const float* Ak4 = As + (k8 + tig + 4) * 132;
                    unsigned ahi[4][4], alo[4][4];
#pragma unroll
                    for (int mi = 0; mi < 4; mi++) {
                        int mr = m0w + mi * 16 + groupID;
                        float a0 = Ak[mr],  a1 = Ak[mr + 8];
                        float a2 = Ak4[mr], a3 = Ak4[mr + 8];
                        ahi[mi][0] = tf32hi(a0); alo[mi][0] = tf32cv(a0 - __uint_as_float(ahi[mi][0]));
                        ahi[mi][1] = tf32hi(a1); alo[mi][1] = tf32cv(a1 - __uint_as_float(ahi[mi][1]));
                        ahi[mi][2] = tf32hi(a2); alo[mi][2] = tf32cv(a2 - __uint_as_float(ahi[mi][2]));
                        ahi[mi][3] = tf32hi(a3); alo[mi][3] = tf32cv(a3 - __uint_as_float(ahi[mi][3]));
                    }
                    const float* Bk  = Bs + (k8 + tig) * 132;
                    const float* Bk4 = Bs + (k8 + tig + 4) * 132;
                    unsigned bhi[4][2], blo[4][2];
#pragma unroll
                    for (int ni = 0; ni < 4; ni++) {
                        int nc = n0w + ni * 8 + groupID;
                        float q0 = Bk[nc], q1 = Bk4[nc];
                        bhi[ni][0] = tf32hi(q0); blo[ni][0] = tf32cv(q0 - __uint_as_float(bhi[ni][0]));
                        bhi[ni][1] = tf32hi(q1); blo[ni][1] = tf32cv(q1 - __uint_as_float(bhi[ni][1]));
                    }
#pragma unroll
                    for (int mi = 0; mi < 4; mi++)
#pragma unroll
                        for (int ni = 0; ni < 4; ni++) {
                            MMA_TF32(acc[mi][ni], ahi[mi], bhi[ni]);
                            MMA_TF32(acc[mi][ni], ahi[mi], blo[ni]);
                            MMA_TF32(acc[mi][ni], alo[mi], bhi[ni]);
                        }
                }
                BARG();
            }

            // epilogue: each thread stores 2 float2 per tile (+bias)
#pragma unroll
            for (int mi = 0; mi < 4; mi++) {
                int r0 = m0w + mi * 16 + groupID;
                int tl0 = r0 >> 3,        bl0 = r0 & 7;
                int tl1 = (r0 + 8) >> 3,  bl1 = (r0 + 8) & 7;
                size_t o0 = xbase + (size_t)(mt * 16 + tl0) * 1024 + bl0 * 128;
                size_t o1 = xbase + (size_t)(mt * 16 + tl1) * 1024 + bl1 * 128;
#pragma unroll
                for (int ni = 0; ni < 4; ni++) {
                    int nc = n0w + ni * 8 + tig * 2;
                    float2 v;
                    v.x = acc[mi][ni][0] + bb0[ni];
                    v.y = acc[mi][ni][1] + bb1[ni];
                    *(float2*)&g_X[o0 + nc] = v;
                    v.x = acc[mi][ni][2] + bb0[ni];
                    v.y = acc[mi][ni][3] + bb1[ni];
                    *(float2*)&g_X[o1 + nc] = v;
                }
            }
            BARG();
            if (tid2 == 0) {
                int val = (mt + 1) * 16;
                asm volatile("st.release.cta.b32 [%0], %1;" :: "l"(xprog), "r"(val) : "memory");
            }
        }
    }
}

// =====================================================================
// Kernel 3: emissions (unchanged)
// =====================================================================
__global__ void emis_kernel(const int* __restrict__ lengths,
                            const float* __restrict__ W_out,
                            const float* __restrict__ b_out)
{
    __shared__ float Wsm[KTAG * 2 * HDIM];
    __shared__ float bsm[KTAG];

    const int tid = threadIdx.x;
    for (int i = tid; i < KTAG * 2 * HDIM; i += 256) Wsm[i] = W_out[i];
    if (tid < KTAG) bsm[tid] = b_out[tid];
    __syncthreads();

    const int warp = tid >> 5;
    const int lane = tid & 31;
    const int r = blockIdx.x * 8 + warp;
    const int b = r >> 9;
    const int t = r & 511;
    const int len = lengths[b];
    const int tr  = (t < len) ? (len - 1 - t) : t;
    const int bt = b >> 3, b_l = b & 7;

    const float* hf = g_h + ((size_t)(0 * 8 + bt)) * (TT * 8 * HDIM)
                          + (size_t)t  * (8 * HDIM) + b_l * HDIM;
    const float* hb = g_h + ((size_t)(1 * 8 + bt)) * (TT * 8 * HDIM)
                          + (size_t)tr * (8 * HDIM) + b_l * HDIM;

    float x[16];
#pragma unroll
    for (int i = 0; i < 8; i++) x[i]     = hf[lane + 32 * i];
#pragma unroll
    for (int i = 0; i < 8; i++) x[8 + i] = hb[lane + 32 * i];

    for (int kk = 0; kk < KTAG; kk++) {
        const float* w = Wsm + (size_t)kk * (2 * HDIM);
        float s = 0.f;
#pragma unroll
        for (int i = 0; i < 8; i++) s += x[i]     * w[lane + 32 * i];
#pragma unroll
        for (int i = 0; i < 8; i++) s += x[8 + i] * w[HDIM + lane + 32 * i];
#pragma unroll
        for (int off = 16; off; off >>= 1) s += __shfl_xor_sync(0xffffffffu, s, off);
        if (lane == 0) g_emis[((size_t)b * TT + t) * KTAG + kk] = s + bsm[kk];
    }
}

// =====================================================================
// Kernel 4: Viterbi (unchanged)
// =====================================================================
#define VIT_SMEM 53248
#define VCOMB(av, ai_, bv, bi_) { if ((bv) > (av)) { (av) = (bv); (ai_) = (bi_); } }

__global__ void viterbi_kernel(const int* __restrict__ lengths,
                               const int* __restrict__ stop_id_p,
                               const float* __restrict__ trans,
                               float* __restrict__ out)
{
    extern __shared__ char vsm[];
    float* emis_s = (float*)vsm;
    float* trp    = emis_s + TT * KTAG;
    float* term   = trp + KTAG * 21;
    unsigned char* bp = (unsigned char*)(term + KTAG);

    const int b = blockIdx.x;
    const int lane = threadIdx.x;

    for (int i = lane; i < TT * KTAG; i += 32)
        emis_s[i] = g_emis[(size_t)b * TT * KTAG + i];
    for (int i = lane; i < KTAG * KTAG; i += 32)
        trp[(i / KTAG) * 21 + (i % KTAG)] = trans[i];
    __syncwarp();

    const int len  = lengths[b];
    const int stop = *stop_id_p;
    const float* trl = trp + (lane < KTAG ? lane : 0) * 21;

    float d = 0.f;

    for (int t = 0; t < TT; t++) {
        float em = (lane < KTAG) ? emis_s[t * KTAG + lane] : 0.f;

        float v[KTAG];
#pragma unroll
        for (int p = 0; p < KTAG; p++)
            v[p] = __shfl_sync(0xffffffffu, d, p) + trl[p];

        float w10[10]; int i10[10];
#pragma unroll
        for (int i = 0; i < 10; i++) {
            w10[i] = v[2 * i]; i10[i] = 2 * i;
            VCOMB(w10[i], i10[i], v[2 * i + 1], 2 * i + 1);
        }
        float w5[5]; int i5[5];
#pragma unroll
        for (int i = 0; i < 5; i++) {
            w5[i] = w10[2 * i]; i5[i] = i10[2 * i];
            VCOMB(w5[i], i5[i], w10[2 * i + 1], i10[2 * i + 1]);
        }
        float bv0 = w5[0]; int bi0 = i5[0];
        VCOMB(bv0, bi0, w5[1], i5[1]);
        float bv1 = w5[2]; int bi1 = i5[2];
        VCOMB(bv1, bi1, w5[3], i5[3]);
        VCOMB(bv0, bi0, bv1, bi1);
        VCOMB(bv0, bi0, w5[4], i5[4]);

        bool valid = (t < len);
        if (lane < KTAG) {
            float nd = bv0 + em;
            int bpv  = valid ? bi0 : lane;
            d = valid ? nd : d;
            bp[t * KTAG + lane] = (unsigned char)bpv;
        }
    }

    if (lane < KTAG) term[lane] = d + trp[stop * 21 + lane];
    __syncwarp();

    if (lane == 0) {
        float best = -3.4e38f; int arg = 0;
        for (int j = 0; j < KTAG; j++)
            if (term[j] > best) { best = term[j]; arg = j; }
        out[b] = best;
        float* po = out + BB + (size_t)b * (TT + 1);
        po[TT] = (float)arg;
        int tag = arg;
        for (int t = TT - 1; t >= 0; t--) {
            tag = bp[t * KTAG + tag];
            po[t] = (float)tag;
        }
    }
}

// =====================================================================
// launch
// =====================================================================
extern "C" void kernel_launch(void* const* d_in, const int* in_sizes, int n_in,
                              void* d_out, int out_size)
{
    (void)in_sizes; (void)n_in; (void)out_size;
    const int*   sentence = (const int*)d_in[0];
    const int*   lengths  = (const int*)d_in[1];
    const int*   stop_id  = (const int*)d_in[3];
    const float* emb      = (const float*)d_in[4];
    const float* Wf_ih    = (const float*)d_in[5];
    const float* Wf_hh    = (const float*)d_in[6];
    const float* bf       = (const float*)d_in[7];
    const float* Wb_ih    = (const float*)d_in[8];
    const float* Wb_hh    = (const float*)d_in[9];
    const float* bb       = (const float*)d_in[10];
    const float* W_out    = (const float*)d_in[11];
    const float* b_out    = (const float*)d_in[12];
    const float* trans    = (const float*)d_in[13];
    float* out = (float*)d_out;

    static int attr_set = 0;
    if (!attr_set) {
        cudaFuncSetAttribute(fused_persistent_kernel,
                             cudaFuncAttributeMaxDynamicSharedMemorySize, SMEM_FUSED);
        cudaFuncSetAttribute(viterbi_kernel,
                             cudaFuncAttributeMaxDynamicSharedMemorySize, VIT_SMEM);
        attr_set = 1;
    }

    fused_persistent_kernel<<<GRID_P, 384, SMEM_FUSED>>>(
        sentence, lengths, emb, Wf_ih, bf, Wb_ih, bb, Wf_hh, Wb_hh);

    emis_kernel<<<BB * TT / 8, 256>>>(lengths, W_out, b_out);

    viterbi_kernel<<<BB, 32, VIT_SMEM>>>(lengths, stop_id, trans, out);
}